// round 2
// baseline (speedup 1.0000x reference)
#include <cuda_runtime.h>

// Problem constants (x: (2,8,4,256,384) fp32 -> 16 independent DxHxW volumes)
#define WD   384
#define HT   256
#define DP   4
#define HW   (HT*WD)          // 98304
#define DHW  (DP*HW)          // 393216
#define NIMG 16

#define TW 32                 // tile width  (threads.x)
#define TH 8                  // tile height (threads.y)
#define SW (TW+2)             // 34
#define SH (TH+2)             // 10
#define SD (DP+2)             // 6
#define SMEM_ELEMS (SD*SH*SW) // 2040

#define BONUS 10.0f

__global__ __launch_bounds__(TW*TH)
void cqi_kernel(const float* __restrict__ xg, float* __restrict__ out)
{
    __shared__ float tile[SD][SH][SW];

    const int img = blockIdx.z;
    const int w0  = blockIdx.x * TW;
    const int h0  = blockIdx.y * TH;
    const int tid = threadIdx.y * TW + threadIdx.x;

    const float* __restrict__ xin = xg + (size_t)img * DHW;

    // -------- cooperative tile load with edge clamping (2040 elems / 256 thr) --------
    #pragma unroll
    for (int idx = tid; idx < SMEM_ELEMS; idx += TW*TH) {
        int p   = idx / (SH*SW);
        int r   = idx - p * (SH*SW);
        int row = r / SW;
        int col = r - row * SW;
        int gd = p - 1;   gd = gd < 0 ? 0 : (gd > DP-1 ? DP-1 : gd);
        int gh = h0 + row - 1; gh = gh < 0 ? 0 : (gh > HT-1 ? HT-1 : gh);
        int gw = w0 + col - 1; gw = gw < 0 ? 0 : (gw > WD-1 ? WD-1 : gw);
        tile[p][row][col] = __ldg(xin + gd*HW + gh*WD + gw);
    }
    __syncthreads();

    const int tx = threadIdx.x, ty = threadIdx.y;
    const int w = w0 + tx, h = h0 + ty;

    // -------- pull the 6x3x3 neighborhood column into registers --------
    float v[SD][3][3];
    float pmax[SD];
    #pragma unroll
    for (int p = 0; p < SD; ++p) {
        #pragma unroll
        for (int i = 0; i < 3; ++i)
            #pragma unroll
            for (int j = 0; j < 3; ++j)
                v[p][i][j] = tile[p][ty + i][tx + j];
        float m = v[p][0][0];
        #pragma unroll
        for (int i = 0; i < 3; ++i)
            #pragma unroll
            for (int j = 0; j < 3; ++j)
                m = fmaxf(m, v[p][i][j]);
        pmax[p] = m;
    }

    float* __restrict__ ocoord = out + (size_t)img * 3 * DHW;
    float* __restrict__ oy     = out + (size_t)NIMG * 3 * DHW + (size_t)img * DHW;

    #pragma unroll
    for (int d = 0; d < DP; ++d) {
        // A = depth d-1 (plane d), Bc = depth d (plane d+1), Cc = depth d+1 (plane d+2)
        const float (*A )[3] = v[d];
        const float (*Bc)[3] = v[d+1];
        const float (*Cc)[3] = v[d+2];

        const float xc = Bc[1][1];

        // first-order gradients (depth kernel flipped)
        const float b0 = 0.5f * (Bc[1][2] - Bc[1][0]);   // dx
        const float b1 = 0.5f * (Bc[2][1] - Bc[0][1]);   // dy
        const float b2 = 0.5f * (A[1][1]  - Cc[1][1]);   // ds (flipped)

        // Hessian
        const float dxx = Bc[1][2] - 2.0f*xc + Bc[1][0];
        const float dyy = Bc[2][1] - 2.0f*xc + Bc[0][1];
        const float dss = Cc[1][1] - 2.0f*xc + A[1][1];
        const float dxy = 0.25f * ( Bc[0][0] - Bc[0][2] - Bc[2][0] + Bc[2][2]);
        const float dys = 0.25f * (-A[0][1]  + A[2][1]  + Cc[0][1] - Cc[2][1]);
        const float dxs = 0.25f * (-A[1][0]  + A[1][2]  + Cc[1][0] - Cc[1][2]);

        // 3x3x3 NMS: clamped 27-set max == -inf padded window max
        const float mx = fmaxf(fmaxf(pmax[d], pmax[d+1]), pmax[d+2]);
        const bool nms = (xc == mx);

        // symmetric 3x3 solve via adjugate/det
        const float c00 = dyy*dss - dys*dys;
        const float c01 = dxs*dys - dxy*dss;
        const float c02 = dxy*dys - dxs*dyy;
        const float c11 = dxx*dss - dxs*dxs;
        const float c12 = dxy*dxs - dxx*dys;
        const float c22 = dxx*dyy - dxy*dxy;
        const float det = dxx*c00 + dxy*c01 + dxs*c02;

        const bool ok = nms && (det != 0.0f);
        const float invdet = 1.0f / ((det == 0.0f) ? 1.0f : det);

        const float u0 = (c00*b0 + c01*b1 + c02*b2) * invdet;
        const float u1 = (c01*b0 + c11*b1 + c12*b2) * invdet;
        const float u2 = (c02*b0 + c12*b1 + c22*b2) * invdet;

        float d0 = ok ? -u0 : 0.0f;
        float d1 = ok ? -u1 : 0.0f;
        float d2 = ok ? -u2 : 0.0f;

        const bool small = fmaxf(fmaxf(fabsf(d0), fabsf(d1)), fabsf(d2)) <= 0.7f;
        d0 = small ? d0 : 0.0f;
        d1 = small ? d1 : 0.0f;
        d2 = small ? d2 : 0.0f;

        const float dE = 0.5f * (b0*d0 + b1*d1 + b2*d2);
        const float y  = xc + dE + (ok ? BONUS : 0.0f);

        const int o = d*HW + h*WD + w;
        ocoord[0*DHW + o] = (float)d + d2;   // depth coord
        ocoord[1*DHW + o] = (float)w + d0;   // x (width) coord
        ocoord[2*DHW + o] = (float)h + d1;   // y (height) coord
        oy[o] = y;
    }
}

extern "C" void kernel_launch(void* const* d_in, const int* in_sizes, int n_in,
                              void* d_out, int out_size)
{
    const float* x = (const float*)d_in[0];
    float* out = (float*)d_out;
    dim3 block(TW, TH, 1);
    dim3 grid(WD / TW, HT / TH, NIMG);
    cqi_kernel<<<grid, block>>>(x, out);
}